// round 3
// baseline (speedup 1.0000x reference)
#include <cuda_runtime.h>
#include <math.h>

// Problem dimensions (fixed by the reference)
constexpr int T  = 2048;   // tokens
constexpr int Hd = 2048;   // hidden
constexpr int E  = 32;     // experts
constexpr int TK = 8;      // top-k
constexpr int Id = 1408;   // intermediate (routed and shared)
constexpr int MAXTILES = 512;

// ---------------- scratch (static device globals; no allocation) ----------------
__device__ int   g_topk[T * TK];
__device__ float g_wt[T * TK];
__device__ int   g_cnt[E];
__device__ int   g_off[E + 1];
__device__ int   g_cur[E];
__device__ int   g_rowtok[T * TK];   // sorted row -> token
__device__ int   g_pos[T * TK];      // (t,k) -> sorted row
__device__ int   g_tile_e[MAXTILES];
__device__ int   g_tile_r[MAXTILES];
__device__ int   g_ntiles;
__device__ float g_h[(size_t)T * TK * Id];   // 92 MB intermediate (silu(g)*u), sorted rows
__device__ float g_y[(size_t)T * TK * Hd];   // 134 MB down-proj per sorted row
__device__ float g_sh[(size_t)T * Id];       // shared-expert intermediate

// ---------------- packed f32x2 helpers (sm_100+ FFMA2) ----------------
#define FMA2(c, a, b) \
    asm("fma.rn.f32x2 %0, %1, %2, %0;" : "+l"(c) : "l"(a), "l"(b))
#define UNPACK2(lo, hi, v) \
    asm("mov.b64 {%0, %1}, %2;" : "=f"(lo), "=f"(hi) : "l"(v))

__device__ __forceinline__ float silu_mul(float g, float u) {
    return g / (1.f + expf(-g)) * u;
}

// ---------------- small kernels ----------------
__global__ void zero_cnt_kernel() {
    int i = threadIdx.x;
    if (i < E) g_cnt[i] = 0;
}

// One block per token: 8 warps compute 32 expert logits, warp 0 does sigmoid + top-8.
__global__ void gate_kernel(const float* __restrict__ x,
                            const float* __restrict__ gw,
                            const float* __restrict__ gbias) {
    int t = blockIdx.x;
    __shared__ float slog[E];
    int warp = threadIdx.x >> 5, lane = threadIdx.x & 31;
    const float* xt = x + (size_t)t * Hd;
    for (int ee = 0; ee < 4; ee++) {
        int e = warp * 4 + ee;
        const float* we = gw + (size_t)e * Hd;
        float s = 0.f;
        for (int i = lane; i < Hd; i += 32) s += xt[i] * we[i];
        for (int o = 16; o; o >>= 1) s += __shfl_xor_sync(0xFFFFFFFFu, s, o);
        if (lane == 0) slog[e] = s;
    }
    __syncthreads();
    if (warp == 0) {
        float sc = 1.f / (1.f + expf(-slog[lane]));   // sigmoid score (weights)
        float sb = sc + gbias[lane];                  // biased score (selection only)
        float myb = sb;
        float wsum = 0.f;
        float my_sc = 0.f;   // lane k latches the k-th winner's score
        int   my_e  = 0;
        #pragma unroll
        for (int k = 0; k < TK; k++) {
            float v = myb; int id = lane;
            #pragma unroll
            for (int o = 16; o; o >>= 1) {
                float v2 = __shfl_xor_sync(0xFFFFFFFFu, v, o);
                int  i2 = __shfl_xor_sync(0xFFFFFFFFu, id, o);
                if (v2 > v || (v2 == v && i2 < id)) { v = v2; id = i2; }
            }
            // convergent gather of the winner's (unbiased) score — all 32 lanes
            float ssc = __shfl_sync(0xFFFFFFFFu, sc, id);
            wsum += ssc;
            if (lane == k) { my_e = id; my_sc = ssc; }
            if (lane == id) myb = -1e30f;
        }
        if (lane < TK) {
            g_topk[t * TK + lane] = my_e;
            g_wt[t * TK + lane]   = my_sc / wsum;
            atomicAdd(&g_cnt[my_e], 1);
        }
    }
}

__global__ void scan_kernel() {
    if (threadIdx.x == 0 && blockIdx.x == 0) {
        int off = 0, nt = 0;
        for (int e = 0; e < E; e++) {
            g_off[e] = off;
            int c = g_cnt[e];
            int ntile = (c + 63) >> 6;
            for (int r = 0; r < ntile; r++) { g_tile_e[nt] = e; g_tile_r[nt] = r; nt++; }
            off += c;
            g_cur[e] = 0;
        }
        g_off[E] = off;
        g_ntiles = nt;
    }
}

__global__ void scatter_kernel() {
    int i = blockIdx.x * blockDim.x + threadIdx.x;
    if (i < T * TK) {
        int e = g_topk[i];
        int p = g_off[e] + atomicAdd(&g_cur[e], 1);
        g_rowtok[p] = i >> 3;   // token index
        g_pos[i] = p;
    }
}

// ---------------- tiled GEMM: BM=BN=64, BK=16, 256 threads, 4x4 per thread ----------------
// GATED: C = silu(A@B1) * (A@B3)      else: C = A@B1
// ROUTED: block maps through the expert tile map; B advanced by expert offset.
// GATHER: A row fetched via g_rowtok (for routed-up from x).
template<bool GATED, bool ROUTED, bool GATHER>
__global__ __launch_bounds__(256)
void gemm_k(const float* __restrict__ A, const float* __restrict__ B1,
            const float* __restrict__ B3, float* __restrict__ C,
            int Kdim, int N, int Mtot) {
    __shared__ float As[64][20];     // [row][k], padded row pitch 20 floats
    __shared__ float Bs1[16][64];
    __shared__ float Bs3[16][64];

    int rowbase, rowlim;
    const float *b1 = B1, *b3 = B3;
    if constexpr (ROUTED) {
        int bx = blockIdx.x;
        if (bx >= g_ntiles) return;
        int e = g_tile_e[bx];
        rowbase = g_off[e] + g_tile_r[bx] * 64;
        rowlim  = g_off[e + 1];
        size_t woff = (size_t)e * Kdim * N;
        b1 = B1 + woff;
        if constexpr (GATED) b3 = B3 + woff;
    } else {
        rowbase = blockIdx.x * 64;
        rowlim  = Mtot;
    }
    int nrows = rowlim - rowbase;
    if (nrows > 64) nrows = 64;
    int n0 = blockIdx.y * 64;
    int tid = threadIdx.x;
    int tx = tid & 15, ty = tid >> 4;

    // A-tile loader indices: thread -> (row=tid/4, k-offset=(tid%4)*4)
    int ar = tid >> 2;
    int ak = (tid & 3) * 4;
    const float* arow = nullptr;
    if (ar < nrows) {
        int grow = rowbase + ar;
        int src = GATHER ? g_rowtok[grow] : grow;
        arow = A + (size_t)src * Kdim;
    }
    // B-tile loader indices
    int bk = tid >> 4;
    int bn = (tid & 15) * 4;
    const float* bp1 = b1 + (size_t)bk * N + n0 + bn;
    const float* bp3 = nullptr;
    if constexpr (GATED) bp3 = b3 + (size_t)bk * N + n0 + bn;

    unsigned long long accg[4][2] = {};
    unsigned long long accu[4][2] = {};

    for (int k0 = 0; k0 < Kdim; k0 += 16) {
        float4 av = make_float4(0.f, 0.f, 0.f, 0.f);
        if (arow) av = *reinterpret_cast<const float4*>(arow + k0 + ak);
        *reinterpret_cast<float4*>(&As[ar][ak]) = av;
        *reinterpret_cast<float4*>(&Bs1[bk][bn]) =
            *reinterpret_cast<const float4*>(bp1 + (size_t)k0 * N);
        if constexpr (GATED)
            *reinterpret_cast<float4*>(&Bs3[bk][bn]) =
                *reinterpret_cast<const float4*>(bp3 + (size_t)k0 * N);
        __syncthreads();
        #pragma unroll
        for (int kk = 0; kk < 16; kk++) {
            unsigned long long b1p0 = *reinterpret_cast<const unsigned long long*>(&Bs1[kk][tx * 4]);
            unsigned long long b1p1 = *reinterpret_cast<const unsigned long long*>(&Bs1[kk][tx * 4 + 2]);
            unsigned long long b3p0 = 0, b3p1 = 0;
            if constexpr (GATED) {
                b3p0 = *reinterpret_cast<const unsigned long long*>(&Bs3[kk][tx * 4]);
                b3p1 = *reinterpret_cast<const unsigned long long*>(&Bs3[kk][tx * 4 + 2]);
            }
            #pragma unroll
            for (int i = 0; i < 4; i++) {
                unsigned int au = __float_as_uint(As[ty * 4 + i][kk]);
                unsigned long long a2;
                asm("mov.b64 %0, {%1, %2};" : "=l"(a2) : "r"(au), "r"(au));
                FMA2(accg[i][0], a2, b1p0);
                FMA2(accg[i][1], a2, b1p1);
                if constexpr (GATED) {
                    FMA2(accu[i][0], a2, b3p0);
                    FMA2(accu[i][1], a2, b3p1);
                }
            }
        }
        __syncthreads();
    }

    #pragma unroll
    for (int i = 0; i < 4; i++) {
        int r = ty * 4 + i;
        if (r >= nrows) continue;
        float g0, g1, g2, g3;
        UNPACK2(g0, g1, accg[i][0]);
        UNPACK2(g2, g3, accg[i][1]);
        float4 ov;
        if constexpr (GATED) {
            float u0, u1, u2, u3;
            UNPACK2(u0, u1, accu[i][0]);
            UNPACK2(u2, u3, accu[i][1]);
            ov.x = silu_mul(g0, u0);
            ov.y = silu_mul(g1, u1);
            ov.z = silu_mul(g2, u2);
            ov.w = silu_mul(g3, u3);
        } else {
            ov = make_float4(g0, g1, g2, g3);
        }
        *reinterpret_cast<float4*>(
            &C[(size_t)(rowbase + r) * N + n0 + tx * 4]) = ov;
    }
}

// out[t,h] (already holds shared-expert result) += sum_k w[t,k] * y[pos(t,k), h]
__global__ void combine_kernel(float* __restrict__ out) {
    int t = blockIdx.x;
    int h = blockIdx.y * 256 + threadIdx.x;
    float acc = out[(size_t)t * Hd + h];
    #pragma unroll
    for (int k = 0; k < TK; k++) {
        int p = g_pos[t * TK + k];
        acc += g_wt[t * TK + k] * g_y[(size_t)p * Hd + h];
    }
    out[(size_t)t * Hd + h] = acc;
}

// ---------------- launch ----------------
extern "C" void kernel_launch(void* const* d_in, const int* in_sizes, int n_in,
                              void* d_out, int out_size) {
    const float* x   = (const float*)d_in[0];
    const float* gw  = (const float*)d_in[1];
    const float* gb  = (const float*)d_in[2];
    const float* w1  = (const float*)d_in[3];
    const float* w3  = (const float*)d_in[4];
    const float* w2  = (const float*)d_in[5];
    const float* sw1 = (const float*)d_in[6];
    const float* sw3 = (const float*)d_in[7];
    const float* sw2 = (const float*)d_in[8];
    float* out = (float*)d_out;

    float *ph = nullptr, *py = nullptr, *psh = nullptr;
    cudaGetSymbolAddress((void**)&ph,  g_h);
    cudaGetSymbolAddress((void**)&py,  g_y);
    cudaGetSymbolAddress((void**)&psh, g_sh);

    zero_cnt_kernel<<<1, 64>>>();
    gate_kernel<<<T, 256>>>(x, gw, gb);
    scan_kernel<<<1, 32>>>();
    scatter_kernel<<<(T * TK) / 256, 256>>>();

    // routed up: h = silu(x@w1[e]) * (x@w3[e])   [sorted rows]
    gemm_k<true, true, true><<<dim3(288, Id / 64), 256>>>(x, w1, w3, ph, Hd, Id, 0);
    // routed down: y = h @ w2[e]
    gemm_k<false, true, false><<<dim3(288, Hd / 64), 256>>>(ph, w2, nullptr, py, Id, Hd, 0);
    // shared up: sh = silu(x@sw1) * (x@sw3)
    gemm_k<true, false, false><<<dim3(T / 64, Id / 64), 256>>>(x, sw1, sw3, psh, Hd, Id, T);
    // shared down: out = sh @ sw2
    gemm_k<false, false, false><<<dim3(T / 64, Hd / 64), 256>>>(psh, sw2, nullptr, out, Id, Hd, T);
    // combine routed with weights into out
    combine_kernel<<<dim3(T, Hd / 256), 256>>>(out);
}

// round 5
// speedup vs baseline: 2.8746x; 2.8746x over previous
#include <cuda_runtime.h>
#include <math.h>

// Problem dimensions (fixed by the reference)
constexpr int T  = 2048;   // tokens
constexpr int Hd = 2048;   // hidden
constexpr int E  = 32;     // experts
constexpr int TK = 8;      // top-k
constexpr int Id = 1408;   // intermediate (routed and shared)
constexpr int MAXTILES = 512;

// ---------------- scratch (static device globals; no allocation) ----------------
__device__ int   g_topk[T * TK];
__device__ float g_wt[T * TK];
__device__ int   g_cnt[E];
__device__ int   g_off[E + 1];
__device__ int   g_cur[E];
__device__ int   g_rowtok[T * TK];   // sorted row -> token
__device__ int   g_pos[T * TK];      // (t,k) -> sorted row
__device__ int   g_tile_e[MAXTILES];
__device__ int   g_tile_r[MAXTILES];
__device__ int   g_ntiles;
__device__ float g_h[(size_t)T * TK * Id];   // intermediate silu(g)*u, sorted rows
__device__ float g_y[(size_t)T * TK * Hd];   // down-proj per sorted row
__device__ float g_sh[(size_t)T * Id];       // shared-expert intermediate

__device__ __forceinline__ float silu_mul(float g, float u) {
    return g / (1.f + expf(-g)) * u;
}

// ---------------- tf32 mma + cp.async helpers ----------------
__device__ __forceinline__ void mma_tf32(float c[4], const unsigned a[4], const unsigned b[2]) {
    asm volatile(
        "mma.sync.aligned.m16n8k8.row.col.f32.tf32.tf32.f32 "
        "{%0,%1,%2,%3}, {%4,%5,%6,%7}, {%8,%9}, {%0,%1,%2,%3};"
        : "+f"(c[0]), "+f"(c[1]), "+f"(c[2]), "+f"(c[3])
        : "r"(a[0]), "r"(a[1]), "r"(a[2]), "r"(a[3]), "r"(b[0]), "r"(b[1]));
}

// Round-to-nearest tf32 conversion. CRITICAL: raw fp32 bits get TRUNCATED by
// the tensor core (biased error ~ -2^-11 per product, survives K-summation);
// cvt.rna makes the error zero-mean so it sqrt(K)-averages out.
__device__ __forceinline__ unsigned f2tf32(float f) {
    unsigned r;
    asm("cvt.rna.tf32.f32 %0, %1;" : "=r"(r) : "f"(f));
    return r;
}

__device__ __forceinline__ void cp_async16(void* smem, const void* gmem, bool pred) {
    unsigned s = (unsigned)__cvta_generic_to_shared(smem);
    int sz = pred ? 16 : 0;   // src-size 0 -> zero-fill 16B
    asm volatile("cp.async.cg.shared.global [%0], [%1], 16, %2;\n"
                 :: "r"(s), "l"(gmem), "r"(sz));
}
#define CP_COMMIT()  asm volatile("cp.async.commit_group;\n" ::: "memory")
#define CP_WAIT(n)   asm volatile("cp.async.wait_group %0;\n" :: "n"(n) : "memory")

// ---------------- small kernels ----------------
__global__ void zero_cnt_kernel() {
    int i = threadIdx.x;
    if (i < E) g_cnt[i] = 0;
}

// One block per token: 8 warps compute 32 expert logits, warp 0 does sigmoid + top-8.
__global__ void gate_kernel(const float* __restrict__ x,
                            const float* __restrict__ gw,
                            const float* __restrict__ gbias) {
    int t = blockIdx.x;
    __shared__ float slog[E];
    int warp = threadIdx.x >> 5, lane = threadIdx.x & 31;
    const float* xt = x + (size_t)t * Hd;
    for (int ee = 0; ee < 4; ee++) {
        int e = warp * 4 + ee;
        const float* we = gw + (size_t)e * Hd;
        float s = 0.f;
        for (int i = lane; i < Hd; i += 32) s += xt[i] * we[i];
        for (int o = 16; o; o >>= 1) s += __shfl_xor_sync(0xFFFFFFFFu, s, o);
        if (lane == 0) slog[e] = s;
    }
    __syncthreads();
    if (warp == 0) {
        float sc = 1.f / (1.f + expf(-slog[lane]));   // sigmoid score (weights)
        float sb = sc + gbias[lane];                  // biased score (selection only)
        float myb = sb;
        float wsum = 0.f;
        float my_sc = 0.f;
        int   my_e  = 0;
        #pragma unroll
        for (int k = 0; k < TK; k++) {
            float v = myb; int id = lane;
            #pragma unroll
            for (int o = 16; o; o >>= 1) {
                float v2 = __shfl_xor_sync(0xFFFFFFFFu, v, o);
                int  i2 = __shfl_xor_sync(0xFFFFFFFFu, id, o);
                if (v2 > v || (v2 == v && i2 < id)) { v = v2; id = i2; }
            }
            float ssc = __shfl_sync(0xFFFFFFFFu, sc, id);   // convergent gather
            wsum += ssc;
            if (lane == k) { my_e = id; my_sc = ssc; }
            if (lane == id) myb = -1e30f;
        }
        if (lane < TK) {
            g_topk[t * TK + lane] = my_e;
            g_wt[t * TK + lane]   = my_sc / wsum;
            atomicAdd(&g_cnt[my_e], 1);
        }
    }
}

__global__ void scan_kernel() {
    if (threadIdx.x == 0 && blockIdx.x == 0) {
        int off = 0, nt = 0;
        for (int e = 0; e < E; e++) {
            g_off[e] = off;
            int c = g_cnt[e];
            int ntile = (c + 127) >> 7;   // 128-row tiles
            for (int r = 0; r < ntile; r++) { g_tile_e[nt] = e; g_tile_r[nt] = r; nt++; }
            off += c;
            g_cur[e] = 0;
        }
        g_off[E] = off;
        g_ntiles = nt;
    }
}

__global__ void scatter_kernel() {
    int i = blockIdx.x * blockDim.x + threadIdx.x;
    if (i < T * TK) {
        int e = g_topk[i];
        int p = g_off[e] + atomicAdd(&g_cur[e], 1);
        g_rowtok[p] = i >> 3;   // token index
        g_pos[i] = p;
    }
}

// ---------------- tf32 tensor-core GEMM ----------------
// BM=128, BN=64, BK=16; 256 threads = 8 warps in 4(m) x 2(n); warp tile 32x32.
// GATED: C = silu(A@B1) * (A@B3)    else C = A@B1
// ROUTED: expert tile map + per-expert weight offset.
// GATHER: A rows fetched via g_rowtok.
template<bool GATED, bool ROUTED, bool GATHER>
__global__ __launch_bounds__(256)
void gemm_mma(const float* __restrict__ A, const float* __restrict__ B1,
              const float* __restrict__ B3, float* __restrict__ C,
              int Kdim, int N, int Mtot) {
    __shared__ float As[2][128][20];              // pitch 20 (conflict-free frag loads)
    __shared__ float Bs1[2][16][68];              // pitch 68
    __shared__ float Bs3[GATED ? 2 : 1][16][68];

    int rowbase, rowlim;
    const float *b1 = B1, *b3 = B3;
    if constexpr (ROUTED) {
        int bx = blockIdx.x;
        if (bx >= g_ntiles) return;
        int e = g_tile_e[bx];
        rowbase = g_off[e] + g_tile_r[bx] * 128;
        rowlim  = g_off[e + 1];
        size_t woff = (size_t)e * Kdim * N;
        b1 = B1 + woff;
        if constexpr (GATED) b3 = B3 + woff;
    } else {
        rowbase = blockIdx.x * 128;
        rowlim  = Mtot;
    }
    int nrows = rowlim - rowbase;
    if (nrows > 128) nrows = 128;
    int n0 = blockIdx.y * 64;
    int tid = threadIdx.x;

    // ---- loader indices ----
    // A: 512 float4 chunks (128 rows x 4 chunks); this thread owns rows ar0, ar0+64.
    int ar0 = tid >> 2;
    int ac  = (tid & 3) * 4;
    const float* aptr0 = nullptr;
    const float* aptr1 = nullptr;
    {
        if (ar0 < nrows) {
            int g = rowbase + ar0;
            int src = GATHER ? g_rowtok[g] : g;
            aptr0 = A + (size_t)src * Kdim + ac;
        }
        if (ar0 + 64 < nrows) {
            int g = rowbase + ar0 + 64;
            int src = GATHER ? g_rowtok[g] : g;
            aptr1 = A + (size_t)src * Kdim + ac;
        }
    }
    // B: 256 float4 chunks (16 k-rows x 16 chunks)
    int br = tid >> 4;
    int bc = (tid & 15) * 4;
    const float* bp1 = b1 + (size_t)br * N + n0 + bc;
    const float* bp3 = nullptr;
    if constexpr (GATED) bp3 = b3 + (size_t)br * N + n0 + bc;

    int nk = Kdim >> 4;

    auto load_stage = [&](int s, int k0) {
        cp_async16(&As[s][ar0][ac],      aptr0 ? aptr0 + k0 : A, aptr0 != nullptr);
        cp_async16(&As[s][ar0 + 64][ac], aptr1 ? aptr1 + k0 : A, aptr1 != nullptr);
        cp_async16(&Bs1[s][br][bc], bp1 + (size_t)k0 * N, true);
        if constexpr (GATED)
            cp_async16(&Bs3[s][br][bc], bp3 + (size_t)k0 * N, true);
        CP_COMMIT();
    };

    float accg[2][4][4] = {};
    float accu[GATED ? 2 : 1][4][4] = {};

    int warp = tid >> 5, lane = tid & 31;
    int wm = (warp & 3) * 32;    // warp row offset in tile
    int wn = (warp >> 2) * 32;   // warp col offset in tile
    int lr = lane >> 2, lc = lane & 3;

    load_stage(0, 0);

    for (int kt = 0; kt < nk; kt++) {
        if (kt + 1 < nk) {
            load_stage((kt + 1) & 1, (kt + 1) * 16);
            CP_WAIT(1);
        } else {
            CP_WAIT(0);
        }
        __syncthreads();
        int s = kt & 1;
        #pragma unroll
        for (int k8 = 0; k8 < 2; k8++) {
            int kb = k8 * 8;
            unsigned a[2][4];
            #pragma unroll
            for (int mt = 0; mt < 2; mt++) {
                int r = wm + mt * 16 + lr;
                a[mt][0] = f2tf32(As[s][r][kb + lc]);
                a[mt][1] = f2tf32(As[s][r + 8][kb + lc]);
                a[mt][2] = f2tf32(As[s][r][kb + lc + 4]);
                a[mt][3] = f2tf32(As[s][r + 8][kb + lc + 4]);
            }
            #pragma unroll
            for (int nt = 0; nt < 4; nt++) {
                int c = wn + nt * 8 + lr;
                unsigned bb[2];
                bb[0] = f2tf32(Bs1[s][kb + lc][c]);
                bb[1] = f2tf32(Bs1[s][kb + lc + 4][c]);
                mma_tf32(accg[0][nt], a[0], bb);
                mma_tf32(accg[1][nt], a[1], bb);
                if constexpr (GATED) {
                    unsigned b3b[2];
                    b3b[0] = f2tf32(Bs3[s][kb + lc][c]);
                    b3b[1] = f2tf32(Bs3[s][kb + lc + 4][c]);
                    mma_tf32(accu[0][nt], a[0], b3b);
                    mma_tf32(accu[1][nt], a[1], b3b);
                }
            }
        }
        __syncthreads();
    }

    // ---- epilogue ----
    #pragma unroll
    for (int mt = 0; mt < 2; mt++) {
        int r0 = wm + mt * 16 + lr;      // row in tile (and r0+8)
        #pragma unroll
        for (int nt = 0; nt < 4; nt++) {
            int col = n0 + wn + nt * 8 + lc * 2;
            float v0, v1, v2, v3;
            if constexpr (GATED) {
                v0 = silu_mul(accg[mt][nt][0], accu[mt][nt][0]);
                v1 = silu_mul(accg[mt][nt][1], accu[mt][nt][1]);
                v2 = silu_mul(accg[mt][nt][2], accu[mt][nt][2]);
                v3 = silu_mul(accg[mt][nt][3], accu[mt][nt][3]);
            } else {
                v0 = accg[mt][nt][0]; v1 = accg[mt][nt][1];
                v2 = accg[mt][nt][2]; v3 = accg[mt][nt][3];
            }
            if (r0 < nrows) {
                float2 p = make_float2(v0, v1);
                *reinterpret_cast<float2*>(&C[(size_t)(rowbase + r0) * N + col]) = p;
            }
            if (r0 + 8 < nrows) {
                float2 p = make_float2(v2, v3);
                *reinterpret_cast<float2*>(&C[(size_t)(rowbase + r0 + 8) * N + col]) = p;
            }
        }
    }
}

// out[t,h] (already holds shared-expert result) += sum_k w[t,k] * y[pos(t,k), h]
__global__ void combine_kernel(float* __restrict__ out) {
    int t = blockIdx.x;
    int h = blockIdx.y * 256 + threadIdx.x;
    float acc = out[(size_t)t * Hd + h];
    #pragma unroll
    for (int k = 0; k < TK; k++) {
        int p = g_pos[t * TK + k];
        acc += g_wt[t * TK + k] * g_y[(size_t)p * Hd + h];
    }
    out[(size_t)t * Hd + h] = acc;
}

// ---------------- launch ----------------
extern "C" void kernel_launch(void* const* d_in, const int* in_sizes, int n_in,
                              void* d_out, int out_size) {
    const float* x   = (const float*)d_in[0];
    const float* gw  = (const float*)d_in[1];
    const float* gb  = (const float*)d_in[2];
    const float* w1  = (const float*)d_in[3];
    const float* w3  = (const float*)d_in[4];
    const float* w2  = (const float*)d_in[5];
    const float* sw1 = (const float*)d_in[6];
    const float* sw3 = (const float*)d_in[7];
    const float* sw2 = (const float*)d_in[8];
    float* out = (float*)d_out;

    float *ph = nullptr, *py = nullptr, *psh = nullptr;
    cudaGetSymbolAddress((void**)&ph,  g_h);
    cudaGetSymbolAddress((void**)&py,  g_y);
    cudaGetSymbolAddress((void**)&psh, g_sh);

    zero_cnt_kernel<<<1, 64>>>();
    gate_kernel<<<T, 256>>>(x, gw, gb);
    scan_kernel<<<1, 32>>>();
    scatter_kernel<<<(T * TK) / 256, 256>>>();

    // Max routed tiles: sum ceil(c_e/128) <= 128 + 31 = 159 -> launch 192, guard inside.
    // routed up: h = silu(x@w1[e]) * (x@w3[e])   [sorted rows, gathered A]
    gemm_mma<true, true, true><<<dim3(192, Id / 64), 256>>>(x, w1, w3, ph, Hd, Id, 0);
    // routed down: y = h @ w2[e]
    gemm_mma<false, true, false><<<dim3(192, Hd / 64), 256>>>(ph, w2, nullptr, py, Id, Hd, 0);
    // shared up: sh = silu(x@sw1) * (x@sw3)
    gemm_mma<true, false, false><<<dim3(T / 128, Id / 64), 256>>>(x, sw1, sw3, psh, Hd, Id, T);
    // shared down: out = sh @ sw2
    gemm_mma<false, false, false><<<dim3(T / 128, Hd / 64), 256>>>(psh, sw2, nullptr, out, Id, Hd, T);
    // combine routed with weights into out
    combine_kernel<<<dim3(T, Hd / 256), 256>>>(out);
}

// round 6
// speedup vs baseline: 3.2986x; 1.1475x over previous
#include <cuda_runtime.h>
#include <math.h>

// Problem dimensions (fixed by the reference)
constexpr int T  = 2048;   // tokens
constexpr int Hd = 2048;   // hidden
constexpr int E  = 32;     // experts
constexpr int TK = 8;      // top-k
constexpr int Id = 1408;   // intermediate (routed and shared)
constexpr int MAXTILES = 512;

// GEMM tile config
constexpr int BM = 128, BN = 128, BK = 32;
constexpr int AP = 36;    // A smem pitch (floats): (4*lr+lc) mod 32 distinct -> 0 conflicts
constexpr int BP = 136;   // B smem pitch (floats): (8*lc+lr) mod 32 distinct -> 0 conflicts

// ---------------- scratch (static device globals; no allocation) ----------------
__device__ int   g_topk[T * TK];
__device__ float g_wt[T * TK];
__device__ int   g_cnt[E];
__device__ int   g_off[E + 1];
__device__ int   g_cur[E];
__device__ int   g_rowtok[T * TK];   // sorted row -> token
__device__ int   g_pos[T * TK];      // (t,k) -> sorted row
__device__ int   g_tile_e[MAXTILES];
__device__ int   g_tile_r[MAXTILES];
__device__ int   g_ntiles;
__device__ float g_h[(size_t)T * TK * Id];   // intermediate silu(g)*u, sorted rows
__device__ float g_y[(size_t)T * TK * Hd];   // down-proj per sorted row
__device__ float g_sh[(size_t)T * Id];       // shared-expert intermediate

__device__ __forceinline__ float silu_mul(float g, float u) {
    return g / (1.f + expf(-g)) * u;
}

// ---------------- tf32 mma + cp.async helpers ----------------
__device__ __forceinline__ void mma_tf32(float c[4], const unsigned a[4], const unsigned b[2]) {
    asm volatile(
        "mma.sync.aligned.m16n8k8.row.col.f32.tf32.tf32.f32 "
        "{%0,%1,%2,%3}, {%4,%5,%6,%7}, {%8,%9}, {%0,%1,%2,%3};"
        : "+f"(c[0]), "+f"(c[1]), "+f"(c[2]), "+f"(c[3])
        : "r"(a[0]), "r"(a[1]), "r"(a[2]), "r"(a[3]), "r"(b[0]), "r"(b[1]));
}

// Round-to-nearest tf32 conversion (raw-bit feed gets truncated -> biased error).
__device__ __forceinline__ unsigned f2tf32(float f) {
    unsigned r;
    asm("cvt.rna.tf32.f32 %0, %1;" : "=r"(r) : "f"(f));
    return r;
}

__device__ __forceinline__ void cp_async16(void* smem, const void* gmem, bool pred) {
    unsigned s = (unsigned)__cvta_generic_to_shared(smem);
    int sz = pred ? 16 : 0;   // src-size 0 -> zero-fill 16B
    asm volatile("cp.async.cg.shared.global [%0], [%1], 16, %2;\n"
                 :: "r"(s), "l"(gmem), "r"(sz));
}
#define CP_COMMIT()  asm volatile("cp.async.commit_group;\n" ::: "memory")
#define CP_WAIT(n)   asm volatile("cp.async.wait_group %0;\n" :: "n"(n) : "memory")

// ---------------- small kernels ----------------
__global__ void zero_cnt_kernel() {
    int i = threadIdx.x;
    if (i < E) g_cnt[i] = 0;
}

// One block per token: 8 warps compute 32 expert logits, warp 0 does sigmoid + top-8.
__global__ void gate_kernel(const float* __restrict__ x,
                            const float* __restrict__ gw,
                            const float* __restrict__ gbias) {
    int t = blockIdx.x;
    __shared__ float slog[E];
    int warp = threadIdx.x >> 5, lane = threadIdx.x & 31;
    const float* xt = x + (size_t)t * Hd;
    for (int ee = 0; ee < 4; ee++) {
        int e = warp * 4 + ee;
        const float* we = gw + (size_t)e * Hd;
        float s = 0.f;
        for (int i = lane; i < Hd; i += 32) s += xt[i] * we[i];
        for (int o = 16; o; o >>= 1) s += __shfl_xor_sync(0xFFFFFFFFu, s, o);
        if (lane == 0) slog[e] = s;
    }
    __syncthreads();
    if (warp == 0) {
        float sc = 1.f / (1.f + expf(-slog[lane]));   // sigmoid score (weights)
        float sb = sc + gbias[lane];                  // biased score (selection only)
        float myb = sb;
        float wsum = 0.f;
        float my_sc = 0.f;
        int   my_e  = 0;
        #pragma unroll
        for (int k = 0; k < TK; k++) {
            float v = myb; int id = lane;
            #pragma unroll
            for (int o = 16; o; o >>= 1) {
                float v2 = __shfl_xor_sync(0xFFFFFFFFu, v, o);
                int  i2 = __shfl_xor_sync(0xFFFFFFFFu, id, o);
                if (v2 > v || (v2 == v && i2 < id)) { v = v2; id = i2; }
            }
            float ssc = __shfl_sync(0xFFFFFFFFu, sc, id);   // convergent gather
            wsum += ssc;
            if (lane == k) { my_e = id; my_sc = ssc; }
            if (lane == id) myb = -1e30f;
        }
        if (lane < TK) {
            g_topk[t * TK + lane] = my_e;
            g_wt[t * TK + lane]   = my_sc / wsum;
            atomicAdd(&g_cnt[my_e], 1);
        }
    }
}

__global__ void scan_kernel() {
    if (threadIdx.x == 0 && blockIdx.x == 0) {
        int off = 0, nt = 0;
        for (int e = 0; e < E; e++) {
            g_off[e] = off;
            int c = g_cnt[e];
            int ntile = (c + 127) >> 7;   // 128-row tiles
            for (int r = 0; r < ntile; r++) { g_tile_e[nt] = e; g_tile_r[nt] = r; nt++; }
            off += c;
            g_cur[e] = 0;
        }
        g_off[E] = off;
        g_ntiles = nt;
    }
}

__global__ void scatter_kernel() {
    int i = blockIdx.x * blockDim.x + threadIdx.x;
    if (i < T * TK) {
        int e = g_topk[i];
        int p = g_off[e] + atomicAdd(&g_cur[e], 1);
        g_rowtok[p] = i >> 3;   // token index
        g_pos[i] = p;
    }
}

// ---------------- tf32 tensor-core GEMM ----------------
// BM=128, BN=128, BK=32; 256 threads = 8 warps in 2(m) x 4(n); warp tile 64x32.
// GATED: C = silu(A@B1) * (A@B3)    else C = A@B1
// ROUTED: expert tile map + per-expert weight offset.
// GATHER: A rows fetched via g_rowtok.
template<bool GATED, bool ROUTED, bool GATHER>
__global__ __launch_bounds__(256, GATED ? 1 : 2)
void gemm_mma(const float* __restrict__ A, const float* __restrict__ B1,
              const float* __restrict__ B3, float* __restrict__ C,
              int Kdim, int N, int Mtot) {
    extern __shared__ float sm[];
    float* sA  = sm;                       // [2][BM][AP]
    float* sB1 = sA + 2 * BM * AP;         // [2][BK][BP]
    float* sB3 = sB1 + 2 * BK * BP;        // [2][BK][BP] (GATED only)

    int rowbase, rowlim;
    const float *b1 = B1, *b3 = B3;
    if constexpr (ROUTED) {
        int bx = blockIdx.x;
        if (bx >= g_ntiles) return;
        int e = g_tile_e[bx];
        rowbase = g_off[e] + g_tile_r[bx] * BM;
        rowlim  = g_off[e + 1];
        size_t woff = (size_t)e * Kdim * N;
        b1 = B1 + woff;
        if constexpr (GATED) b3 = B3 + woff;
    } else {
        rowbase = blockIdx.x * BM;
        rowlim  = Mtot;
    }
    int nrows = rowlim - rowbase;
    if (nrows > BM) nrows = BM;
    int n0 = blockIdx.y * BN;
    int tid = threadIdx.x;

    // ---- loader indices ----
    // A tile: 128 rows x 32 floats = 1024 float4 chunks; thread owns rows ar+32t, col akc.
    int ar  = tid >> 3;           // 0..31
    int akc = (tid & 7) * 4;      // 0,4,..,28
    const float* aptr[4];
    #pragma unroll
    for (int t4 = 0; t4 < 4; t4++) {
        int r = ar + t4 * 32;
        aptr[t4] = nullptr;
        if (r < nrows) {
            int g = rowbase + r;
            int src = GATHER ? g_rowtok[g] : g;
            aptr[t4] = A + (size_t)src * Kdim + akc;
        }
    }
    // B tile: 32 k-rows x 128 floats = 1024 chunks; thread owns rows brr+8t, col bcc.
    int brr = tid >> 5;           // 0..7
    int bcc = (tid & 31) * 4;     // 0..124
    const float* bp1 = b1 + (size_t)brr * N + n0 + bcc;
    const float* bp3 = nullptr;
    if constexpr (GATED) bp3 = b3 + (size_t)brr * N + n0 + bcc;

    int nk = Kdim / BK;

    auto load_stage = [&](int s, int k0) {
        #pragma unroll
        for (int t4 = 0; t4 < 4; t4++) {
            cp_async16(&sA[s * BM * AP + (ar + t4 * 32) * AP + akc],
                       aptr[t4] ? aptr[t4] + k0 : A, aptr[t4] != nullptr);
        }
        #pragma unroll
        for (int t4 = 0; t4 < 4; t4++) {
            cp_async16(&sB1[s * BK * BP + (brr + t4 * 8) * BP + bcc],
                       bp1 + (size_t)(k0 + t4 * 8) * N, true);
            if constexpr (GATED)
                cp_async16(&sB3[s * BK * BP + (brr + t4 * 8) * BP + bcc],
                           bp3 + (size_t)(k0 + t4 * 8) * N, true);
        }
        CP_COMMIT();
    };

    float accg[4][4][4] = {};
    float accu[GATED ? 4 : 1][4][4] = {};

    int warp = tid >> 5, lane = tid & 31;
    int wm = (warp >> 2) * 64;   // warp row offset (0 / 64)
    int wn = (warp & 3) * 32;    // warp col offset (0/32/64/96)
    int lr = lane >> 2, lc = lane & 3;

    load_stage(0, 0);

    for (int kt = 0; kt < nk; kt++) {
        if (kt + 1 < nk) {
            load_stage((kt + 1) & 1, (kt + 1) * BK);
            CP_WAIT(1);
        } else {
            CP_WAIT(0);
        }
        __syncthreads();
        int s = kt & 1;
        const float* As_ = sA + s * BM * AP;
        const float* B1_ = sB1 + s * BK * BP;
        const float* B3_ = sB3 + s * BK * BP;
        #pragma unroll
        for (int k8 = 0; k8 < BK / 8; k8++) {
            int kb = k8 * 8;
            unsigned a[4][4];
            #pragma unroll
            for (int mt = 0; mt < 4; mt++) {
                int r = wm + mt * 16 + lr;
                a[mt][0] = f2tf32(As_[r * AP + kb + lc]);
                a[mt][1] = f2tf32(As_[(r + 8) * AP + kb + lc]);
                a[mt][2] = f2tf32(As_[r * AP + kb + lc + 4]);
                a[mt][3] = f2tf32(As_[(r + 8) * AP + kb + lc + 4]);
            }
            #pragma unroll
            for (int nt = 0; nt < 4; nt++) {
                int c = wn + nt * 8 + lr;
                unsigned bb[2];
                bb[0] = f2tf32(B1_[(kb + lc) * BP + c]);
                bb[1] = f2tf32(B1_[(kb + lc + 4) * BP + c]);
                #pragma unroll
                for (int mt = 0; mt < 4; mt++) mma_tf32(accg[mt][nt], a[mt], bb);
                if constexpr (GATED) {
                    unsigned b3b[2];
                    b3b[0] = f2tf32(B3_[(kb + lc) * BP + c]);
                    b3b[1] = f2tf32(B3_[(kb + lc + 4) * BP + c]);
                    #pragma unroll
                    for (int mt = 0; mt < 4; mt++) mma_tf32(accu[mt][nt], a[mt], b3b);
                }
            }
        }
        __syncthreads();
    }

    // ---- epilogue ----
    #pragma unroll
    for (int mt = 0; mt < 4; mt++) {
        int r0 = wm + mt * 16 + lr;      // row in tile (and r0+8)
        #pragma unroll
        for (int nt = 0; nt < 4; nt++) {
            int col = n0 + wn + nt * 8 + lc * 2;
            float v0, v1, v2, v3;
            if constexpr (GATED) {
                v0 = silu_mul(accg[mt][nt][0], accu[mt][nt][0]);
                v1 = silu_mul(accg[mt][nt][1], accu[mt][nt][1]);
                v2 = silu_mul(accg[mt][nt][2], accu[mt][nt][2]);
                v3 = silu_mul(accg[mt][nt][3], accu[mt][nt][3]);
            } else {
                v0 = accg[mt][nt][0]; v1 = accg[mt][nt][1];
                v2 = accg[mt][nt][2]; v3 = accg[mt][nt][3];
            }
            if (r0 < nrows) {
                float2 p = make_float2(v0, v1);
                *reinterpret_cast<float2*>(&C[(size_t)(rowbase + r0) * N + col]) = p;
            }
            if (r0 + 8 < nrows) {
                float2 p = make_float2(v2, v3);
                *reinterpret_cast<float2*>(&C[(size_t)(rowbase + r0 + 8) * N + col]) = p;
            }
        }
    }
}

// out[t,h] (already holds shared-expert result) += sum_k w[t,k] * y[pos(t,k), h]
__global__ void combine_kernel(float* __restrict__ out) {
    int t = blockIdx.x;
    int h = blockIdx.y * 256 + threadIdx.x;
    float acc = out[(size_t)t * Hd + h];
    #pragma unroll
    for (int k = 0; k < TK; k++) {
        int p = g_pos[t * TK + k];
        acc += g_wt[t * TK + k] * g_y[(size_t)p * Hd + h];
    }
    out[(size_t)t * Hd + h] = acc;
}

// ---------------- launch ----------------
constexpr int SMEM_GATED = (2 * BM * AP + 4 * BK * BP) * 4;   // 106,496 B
constexpr int SMEM_PLAIN = (2 * BM * AP + 2 * BK * BP) * 4;   //  71,680 B

extern "C" void kernel_launch(void* const* d_in, const int* in_sizes, int n_in,
                              void* d_out, int out_size) {
    const float* x   = (const float*)d_in[0];
    const float* gw  = (const float*)d_in[1];
    const float* gb  = (const float*)d_in[2];
    const float* w1  = (const float*)d_in[3];
    const float* w3  = (const float*)d_in[4];
    const float* w2  = (const float*)d_in[5];
    const float* sw1 = (const float*)d_in[6];
    const float* sw3 = (const float*)d_in[7];
    const float* sw2 = (const float*)d_in[8];
    float* out = (float*)d_out;

    float *ph = nullptr, *py = nullptr, *psh = nullptr;
    cudaGetSymbolAddress((void**)&ph,  g_h);
    cudaGetSymbolAddress((void**)&py,  g_y);
    cudaGetSymbolAddress((void**)&psh, g_sh);

    // Raise dynamic smem limits (idempotent host calls; not stream ops).
    cudaFuncSetAttribute(gemm_mma<true, true, true>,
                         cudaFuncAttributeMaxDynamicSharedMemorySize, SMEM_GATED);
    cudaFuncSetAttribute(gemm_mma<false, true, false>,
                         cudaFuncAttributeMaxDynamicSharedMemorySize, SMEM_PLAIN);
    cudaFuncSetAttribute(gemm_mma<true, false, false>,
                         cudaFuncAttributeMaxDynamicSharedMemorySize, SMEM_GATED);
    cudaFuncSetAttribute(gemm_mma<false, false, false>,
                         cudaFuncAttributeMaxDynamicSharedMemorySize, SMEM_PLAIN);

    zero_cnt_kernel<<<1, 64>>>();
    gate_kernel<<<T, 256>>>(x, gw, gb);
    scan_kernel<<<1, 32>>>();
    scatter_kernel<<<(T * TK) / 256, 256>>>();

    // Max routed tiles: sum ceil(c_e/128) <= 128 + 31 = 159 -> launch 192, guard inside.
    // routed up: h = silu(x@w1[e]) * (x@w3[e])   [sorted rows, gathered A]
    gemm_mma<true, true, true><<<dim3(192, Id / BN), 256, SMEM_GATED>>>(
        x, w1, w3, ph, Hd, Id, 0);
    // routed down: y = h @ w2[e]
    gemm_mma<false, true, false><<<dim3(192, Hd / BN), 256, SMEM_PLAIN>>>(
        ph, w2, nullptr, py, Id, Hd, 0);
    // shared up: sh = silu(x@sw1) * (x@sw3)
    gemm_mma<true, false, false><<<dim3(T / BM, Id / BN), 256, SMEM_GATED>>>(
        x, sw1, sw3, psh, Hd, Id, T);
    // shared down: out = sh @ sw2
    gemm_mma<false, false, false><<<dim3(T / BM, Hd / BN), 256, SMEM_PLAIN>>>(
        psh, sw2, nullptr, out, Id, Hd, T);
    // combine routed with weights into out
    combine_kernel<<<dim3(T, Hd / 256), 256>>>(out);
}

// round 8
// speedup vs baseline: 3.3019x; 1.0010x over previous
#include <cuda_runtime.h>
#include <math.h>

// Problem dimensions (fixed by the reference)
constexpr int T  = 2048;   // tokens
constexpr int Hd = 2048;   // hidden
constexpr int E  = 32;     // experts
constexpr int TK = 8;      // top-k
constexpr int Id = 1408;   // intermediate (routed and shared)
constexpr int MAXTILES = 512;

// GEMM tile config
constexpr int BM = 128, BN = 128, BK = 32;
constexpr int AP = 36;    // A smem pitch (floats): (4*lr+lc) mod 32 distinct -> 0 conflicts
constexpr int BP = 136;   // B smem pitch (floats): (8*lc+lr) mod 32 distinct -> 0 conflicts

// ---------------- scratch (static device globals; no allocation) ----------------
__device__ int   g_topk[T * TK];
__device__ float g_wt[T * TK];
__device__ int   g_cnt[E];
__device__ int   g_off[E + 1];
__device__ int   g_cur[E];
__device__ int   g_rowtok[T * TK];   // sorted row -> token
__device__ int   g_pos[T * TK];      // (t,k) -> sorted row
__device__ int   g_tile_e[MAXTILES];
__device__ int   g_tile_r[MAXTILES];
__device__ int   g_ntiles;
__device__ float g_h[(size_t)T * TK * Id];   // intermediate silu(g)*u, sorted rows
__device__ float g_y[(size_t)T * TK * Hd];   // down-proj per sorted row
__device__ float g_sh[(size_t)T * Id];       // shared-expert intermediate

__device__ __forceinline__ float silu_mul(float g, float u) {
    return g / (1.f + expf(-g)) * u;
}

// ---------------- tf32 mma + cp.async helpers ----------------
__device__ __forceinline__ void mma_tf32(float c[4], const unsigned a[4], const unsigned b[2]) {
    asm volatile(
        "mma.sync.aligned.m16n8k8.row.col.f32.tf32.tf32.f32 "
        "{%0,%1,%2,%3}, {%4,%5,%6,%7}, {%8,%9}, {%0,%1,%2,%3};"
        : "+f"(c[0]), "+f"(c[1]), "+f"(c[2]), "+f"(c[3])
        : "r"(a[0]), "r"(a[1]), "r"(a[2]), "r"(a[3]), "r"(b[0]), "r"(b[1]));
}

// Round-to-nearest tf32 conversion (raw-bit feed gets truncated -> biased error).
__device__ __forceinline__ unsigned f2tf32(float f) {
    unsigned r;
    asm("cvt.rna.tf32.f32 %0, %1;" : "=r"(r) : "f"(f));
    return r;
}

__device__ __forceinline__ void cp_async16(void* smem, const void* gmem, bool pred) {
    unsigned s = (unsigned)__cvta_generic_to_shared(smem);
    int sz = pred ? 16 : 0;   // src-size 0 -> zero-fill 16B
    asm volatile("cp.async.cg.shared.global [%0], [%1], 16, %2;\n"
                 :: "r"(s), "l"(gmem), "r"(sz));
}
#define CP_COMMIT()  asm volatile("cp.async.commit_group;\n" ::: "memory")
#define CP_WAIT(n)   asm volatile("cp.async.wait_group %0;\n" :: "n"(n) : "memory")

// ---------------- small kernels ----------------
__global__ void zero_cnt_kernel() {
    int i = threadIdx.x;
    if (i < E) g_cnt[i] = 0;
}

// One block per token: 8 warps compute 32 expert logits, warp 0 does sigmoid + top-8.
__global__ void gate_kernel(const float* __restrict__ x,
                            const float* __restrict__ gw,
                            const float* __restrict__ gbias) {
    int t = blockIdx.x;
    __shared__ float slog[E];
    int warp = threadIdx.x >> 5, lane = threadIdx.x & 31;
    const float* xt = x + (size_t)t * Hd;
    for (int ee = 0; ee < 4; ee++) {
        int e = warp * 4 + ee;
        const float* we = gw + (size_t)e * Hd;
        float s = 0.f;
        for (int i = lane; i < Hd; i += 32) s += xt[i] * we[i];
        for (int o = 16; o; o >>= 1) s += __shfl_xor_sync(0xFFFFFFFFu, s, o);
        if (lane == 0) slog[e] = s;
    }
    __syncthreads();
    if (warp == 0) {
        float sc = 1.f / (1.f + expf(-slog[lane]));   // sigmoid score (weights)
        float sb = sc + gbias[lane];                  // biased score (selection only)
        float myb = sb;
        float wsum = 0.f;
        float my_sc = 0.f;
        int   my_e  = 0;
        #pragma unroll
        for (int k = 0; k < TK; k++) {
            float v = myb; int id = lane;
            #pragma unroll
            for (int o = 16; o; o >>= 1) {
                float v2 = __shfl_xor_sync(0xFFFFFFFFu, v, o);
                int  i2 = __shfl_xor_sync(0xFFFFFFFFu, id, o);
                if (v2 > v || (v2 == v && i2 < id)) { v = v2; id = i2; }
            }
            float ssc = __shfl_sync(0xFFFFFFFFu, sc, id);   // convergent gather
            wsum += ssc;
            if (lane == k) { my_e = id; my_sc = ssc; }
            if (lane == id) myb = -1e30f;
        }
        if (lane < TK) {
            g_topk[t * TK + lane] = my_e;
            g_wt[t * TK + lane]   = my_sc / wsum;
            atomicAdd(&g_cnt[my_e], 1);
        }
    }
}

__global__ void scan_kernel() {
    if (threadIdx.x == 0 && blockIdx.x == 0) {
        int off = 0, nt = 0;
        for (int e = 0; e < E; e++) {
            g_off[e] = off;
            int c = g_cnt[e];
            int ntile = (c + 127) >> 7;   // 128-row tiles
            for (int r = 0; r < ntile; r++) { g_tile_e[nt] = e; g_tile_r[nt] = r; nt++; }
            off += c;
            g_cur[e] = 0;
        }
        g_off[E] = off;
        g_ntiles = nt;
    }
}

__global__ void scatter_kernel() {
    int i = blockIdx.x * blockDim.x + threadIdx.x;
    if (i < T * TK) {
        int e = g_topk[i];
        int p = g_off[e] + atomicAdd(&g_cur[e], 1);
        g_rowtok[p] = i >> 3;   // token index
        g_pos[i] = p;
    }
}

// ---------------- tf32 tensor-core GEMM ----------------
// BM=128, BN=128, BK=32; 256 threads = 8 warps in 2(m) x 4(n); warp tile 64x32.
// GATED: C = silu(A@B1) * (A@B3)    else C = A@B1
// ROUTED: expert tile map + per-expert weight offset.
// GATHER: A rows fetched via g_rowtok.
template<bool GATED, bool ROUTED, bool GATHER>
__global__ __launch_bounds__(256, GATED ? 1 : 2)
void gemm_mma(const float* __restrict__ A, const float* __restrict__ B1,
              const float* __restrict__ B3, float* __restrict__ C,
              int Kdim, int N, int Mtot) {
    extern __shared__ float sm[];
    float* sA  = sm;                       // [2][BM][AP]
    float* sB1 = sA + 2 * BM * AP;         // [2][BK][BP]
    float* sB3 = sB1 + 2 * BK * BP;        // [2][BK][BP] (GATED only)

    int rowbase, rowlim;
    const float *b1 = B1, *b3 = B3;
    if constexpr (ROUTED) {
        int bx = blockIdx.x;
        if (bx >= g_ntiles) return;
        int e = g_tile_e[bx];
        rowbase = g_off[e] + g_tile_r[bx] * BM;
        rowlim  = g_off[e + 1];
        size_t woff = (size_t)e * Kdim * N;
        b1 = B1 + woff;
        if constexpr (GATED) b3 = B3 + woff;
    } else {
        rowbase = blockIdx.x * BM;
        rowlim  = Mtot;
    }
    int nrows = rowlim - rowbase;
    if (nrows > BM) nrows = BM;
    int n0 = blockIdx.y * BN;
    int tid = threadIdx.x;

    // ---- loader indices ----
    // A tile: 128 rows x 32 floats = 1024 float4 chunks; thread owns rows ar+32t, col akc.
    int ar  = tid >> 3;           // 0..31
    int akc = (tid & 7) * 4;      // 0,4,..,28
    const float* aptr[4];
    #pragma unroll
    for (int t4 = 0; t4 < 4; t4++) {
        int r = ar + t4 * 32;
        aptr[t4] = nullptr;
        if (r < nrows) {
            int g = rowbase + r;
            int src = GATHER ? g_rowtok[g] : g;
            aptr[t4] = A + (size_t)src * Kdim + akc;
        }
    }
    // B tile: 32 k-rows x 128 floats = 1024 chunks; thread owns rows brr+8t, col bcc.
    int brr = tid >> 5;           // 0..7
    int bcc = (tid & 31) * 4;     // 0..124
    const float* bp1 = b1 + (size_t)brr * N + n0 + bcc;
    const float* bp3 = nullptr;
    if constexpr (GATED) bp3 = b3 + (size_t)brr * N + n0 + bcc;

    int nk = Kdim / BK;

    auto load_stage = [&](int s, int k0) {
        #pragma unroll
        for (int t4 = 0; t4 < 4; t4++) {
            cp_async16(&sA[s * BM * AP + (ar + t4 * 32) * AP + akc],
                       aptr[t4] ? aptr[t4] + k0 : A, aptr[t4] != nullptr);
        }
        #pragma unroll
        for (int t4 = 0; t4 < 4; t4++) {
            cp_async16(&sB1[s * BK * BP + (brr + t4 * 8) * BP + bcc],
                       bp1 + (size_t)(k0 + t4 * 8) * N, true);
            if constexpr (GATED)
                cp_async16(&sB3[s * BK * BP + (brr + t4 * 8) * BP + bcc],
                           bp3 + (size_t)(k0 + t4 * 8) * N, true);
        }
        CP_COMMIT();
    };

    float accg[4][4][4] = {};
    float accu[GATED ? 4 : 1][4][4] = {};

    int warp = tid >> 5, lane = tid & 31;
    int wm = (warp >> 2) * 64;   // warp row offset (0 / 64)
    int wn = (warp & 3) * 32;    // warp col offset (0/32/64/96)
    int lr = lane >> 2, lc = lane & 3;

    load_stage(0, 0);

    for (int kt = 0; kt < nk; kt++) {
        if (kt + 1 < nk) {
            load_stage((kt + 1) & 1, (kt + 1) * BK);
            CP_WAIT(1);
        } else {
            CP_WAIT(0);
        }
        __syncthreads();
        int s = kt & 1;
        const float* As_ = sA + s * BM * AP;
        const float* B1_ = sB1 + s * BK * BP;
        const float* B3_ = sB3 + s * BK * BP;
        #pragma unroll
        for (int k8 = 0; k8 < BK / 8; k8++) {
            int kb = k8 * 8;
            unsigned a[4][4];
            #pragma unroll
            for (int mt = 0; mt < 4; mt++) {
                int r = wm + mt * 16 + lr;
                a[mt][0] = f2tf32(As_[r * AP + kb + lc]);
                a[mt][1] = f2tf32(As_[(r + 8) * AP + kb + lc]);
                a[mt][2] = f2tf32(As_[r * AP + kb + lc + 4]);
                a[mt][3] = f2tf32(As_[(r + 8) * AP + kb + lc + 4]);
            }
            #pragma unroll
            for (int nt = 0; nt < 4; nt++) {
                int c = wn + nt * 8 + lr;
                unsigned bb[2];
                bb[0] = f2tf32(B1_[(kb + lc) * BP + c]);
                bb[1] = f2tf32(B1_[(kb + lc + 4) * BP + c]);
                #pragma unroll
                for (int mt = 0; mt < 4; mt++) mma_tf32(accg[mt][nt], a[mt], bb);
                if constexpr (GATED) {
                    unsigned b3b[2];
                    b3b[0] = f2tf32(B3_[(kb + lc) * BP + c]);
                    b3b[1] = f2tf32(B3_[(kb + lc + 4) * BP + c]);
                    #pragma unroll
                    for (int mt = 0; mt < 4; mt++) mma_tf32(accu[mt][nt], a[mt], b3b);
                }
            }
        }
        __syncthreads();
    }

    // ---- epilogue ----
    #pragma unroll
    for (int mt = 0; mt < 4; mt++) {
        int r0 = wm + mt * 16 + lr;      // row in tile (and r0+8)
        #pragma unroll
        for (int nt = 0; nt < 4; nt++) {
            int col = n0 + wn + nt * 8 + lc * 2;
            float v0, v1, v2, v3;
            if constexpr (GATED) {
                v0 = silu_mul(accg[mt][nt][0], accu[mt][nt][0]);
                v1 = silu_mul(accg[mt][nt][1], accu[mt][nt][1]);
                v2 = silu_mul(accg[mt][nt][2], accu[mt][nt][2]);
                v3 = silu_mul(accg[mt][nt][3], accu[mt][nt][3]);
            } else {
                v0 = accg[mt][nt][0]; v1 = accg[mt][nt][1];
                v2 = accg[mt][nt][2]; v3 = accg[mt][nt][3];
            }
            if (r0 < nrows) {
                float2 p = make_float2(v0, v1);
                *reinterpret_cast<float2*>(&C[(size_t)(rowbase + r0) * N + col]) = p;
            }
            if (r0 + 8 < nrows) {
                float2 p = make_float2(v2, v3);
                *reinterpret_cast<float2*>(&C[(size_t)(rowbase + r0 + 8) * N + col]) = p;
            }
        }
    }
}

// out[t,h] (already holds shared-expert result) += sum_k w[t,k] * y[pos(t,k), h]
__global__ void combine_kernel(float* __restrict__ out) {
    int t = blockIdx.x;
    int h = blockIdx.y * 256 + threadIdx.x;
    float acc = out[(size_t)t * Hd + h];
    #pragma unroll
    for (int k = 0; k < TK; k++) {
        int p = g_pos[t * TK + k];
        acc += g_wt[t * TK + k] * g_y[(size_t)p * Hd + h];
    }
    out[(size_t)t * Hd + h] = acc;
}

// ---------------- launch ----------------
constexpr int SMEM_GATED = (2 * BM * AP + 4 * BK * BP) * 4;   // 106,496 B
constexpr int SMEM_PLAIN = (2 * BM * AP + 2 * BK * BP) * 4;   //  71,680 B

extern "C" void kernel_launch(void* const* d_in, const int* in_sizes, int n_in,
                              void* d_out, int out_size) {
    const float* x   = (const float*)d_in[0];
    const float* gw  = (const float*)d_in[1];
    const float* gb  = (const float*)d_in[2];
    const float* w1  = (const float*)d_in[3];
    const float* w3  = (const float*)d_in[4];
    const float* w2  = (const float*)d_in[5];
    const float* sw1 = (const float*)d_in[6];
    const float* sw3 = (const float*)d_in[7];
    const float* sw2 = (const float*)d_in[8];
    float* out = (float*)d_out;

    float *ph = nullptr, *py = nullptr, *psh = nullptr;
    cudaGetSymbolAddress((void**)&ph,  g_h);
    cudaGetSymbolAddress((void**)&py,  g_y);
    cudaGetSymbolAddress((void**)&psh, g_sh);

    // Raise dynamic smem limits (idempotent host calls; not stream ops).
    cudaFuncSetAttribute(gemm_mma<true, true, true>,
                         cudaFuncAttributeMaxDynamicSharedMemorySize, SMEM_GATED);
    cudaFuncSetAttribute(gemm_mma<false, true, false>,
                         cudaFuncAttributeMaxDynamicSharedMemorySize, SMEM_PLAIN);
    cudaFuncSetAttribute(gemm_mma<true, false, false>,
                         cudaFuncAttributeMaxDynamicSharedMemorySize, SMEM_GATED);
    cudaFuncSetAttribute(gemm_mma<false, false, false>,
                         cudaFuncAttributeMaxDynamicSharedMemorySize, SMEM_PLAIN);

    zero_cnt_kernel<<<1, 64>>>();
    gate_kernel<<<T, 256>>>(x, gw, gb);
    scan_kernel<<<1, 32>>>();
    scatter_kernel<<<(T * TK) / 256, 256>>>();

    // Max routed tiles: sum ceil(c_e/128) <= 128 + 31 = 159 -> launch 192, guard inside.
    // routed up: h = silu(x@w1[e]) * (x@w3[e])   [sorted rows, gathered A]
    gemm_mma<true, true, true><<<dim3(192, Id / BN), 256, SMEM_GATED>>>(
        x, w1, w3, ph, Hd, Id, 0);
    // routed down: y = h @ w2[e]
    gemm_mma<false, true, false><<<dim3(192, Hd / BN), 256, SMEM_PLAIN>>>(
        ph, w2, nullptr, py, Id, Hd, 0);
    // shared up: sh = silu(x@sw1) * (x@sw3)
    gemm_mma<true, false, false><<<dim3(T / BM, Id / BN), 256, SMEM_GATED>>>(
        x, sw1, sw3, psh, Hd, Id, T);
    // shared down: out = sh @ sw2
    gemm_mma<false, false, false><<<dim3(T / BM, Hd / BN), 256, SMEM_PLAIN>>>(
        psh, sw2, nullptr, out, Id, Hd, T);
    // combine routed with weights into out
    combine_kernel<<<dim3(T, Hd / 256), 256>>>(out);
}